// round 11
// baseline (speedup 1.0000x reference)
#include <cuda_runtime.h>
#include <math.h>

// Problem constants (fixed by the dataset)
#define NN    50000
#define FDIM  160
#define KD    160
#define G4    640
#define DEG   16
#define OUTC  128
#define HS    16              // hidden units per col-group
#define CG    64              // cols per col-group (HS hidden x 4 gates)
#define NCG   10              // col groups (160 / HS)
#define MT    64              // M tile (nodes per tile)
#define SLOTS 29              // mt-slots per col group
#define GRID  (NCG * SLOTS)   // 290 persistent CTAs (fits 2/SM on 148 SMs)

typedef unsigned long long ull;
typedef unsigned int uint;

// Scratch (device globals — no runtime allocation allowed)
__device__ float g_hin [(size_t)NN * FDIM];   // concat(x, emb)
__device__ float g_gall[(size_t)NN * G4];     // permuted (hidden*4+gate) input gates
__device__ float g_rout[(size_t)NN * OUTC];   // h_in@W_r^T + b_l
__device__ float g_h0  [(size_t)NN * FDIM];   // h ping (tf32-rounded values)
__device__ float g_h1  [(size_t)NN * FDIM];   // h pong
__device__ float g_c   [(size_t)NN * FDIM];   // cell state (full fp32)
__device__ unsigned g_arrive;                 // grid-barrier counter

// ---------------------------------------------------------------------------
// helpers
// ---------------------------------------------------------------------------
__device__ __forceinline__ uint tf32c(float x) {
    uint r; asm("cvt.rna.tf32.f32 %0, %1;" : "=r"(r) : "f"(x)); return r;
}
__device__ __forceinline__ void mma8(float& d0, float& d1, float& d2, float& d3,
                                     uint a0, uint a1, uint a2, uint a3,
                                     uint b0, uint b1) {
    asm volatile("mma.sync.aligned.m16n8k8.row.col.f32.tf32.tf32.f32 "
                 "{%0,%1,%2,%3},{%4,%5,%6,%7},{%8,%9},{%0,%1,%2,%3};"
                 : "+f"(d0), "+f"(d1), "+f"(d2), "+f"(d3)
                 : "r"(a0), "r"(a1), "r"(a2), "r"(a3), "r"(b0), "r"(b1));
}
__device__ __forceinline__ ull ffma2(ull a, ull b, ull c) {
    ull d; asm("fma.rn.f32x2 %0, %1, %2, %3;" : "=l"(d) : "l"(a), "l"(b), "l"(c));
    return d;
}
__device__ __forceinline__ ull dup2(float x) {
    ull r; asm("mov.b64 %0, {%1, %1};" : "=l"(r) : "f"(x)); return r;
}
__device__ __forceinline__ float2 unpk(ull v) {
    float2 r; asm("mov.b64 {%0, %1}, %2;" : "=f"(r.x), "=f"(r.y) : "l"(v)); return r;
}
__device__ __forceinline__ float sigm(float x)     { return 1.f / (1.f + __expf(-x)); }
__device__ __forceinline__ float tanhfast(float x) { return 1.f - 2.f / (1.f + __expf(2.f * x)); }

#define CP16(dst, src) asm volatile("cp.async.cg.shared.global [%0], [%1], 16;" \
                                    :: "r"(dst), "l"(src))
#define CPCOMMIT() asm volatile("cp.async.commit_group;" ::: "memory")
#define CPWAIT1()  asm volatile("cp.async.wait_group 1;" ::: "memory")

// Dynamic SMEM layout (floats): Wu[64][164] then 2x Gsh[64][68]
#define G_OFF 10496
#define GBUF  4352
#define PERSIST_SMEM ((10496 + 2 * GBUF) * 4)   // 76800 B  -> 2 CTAs/SM
#define PRE_SMEM  (14848 * 4)

// ---------------------------------------------------------------------------
// barrier reset (one graph node per replay, before the persistent kernel)
// ---------------------------------------------------------------------------
__global__ void reset_kernel() { g_arrive = 0u; }

__device__ __forceinline__ void grid_barrier(unsigned target) {
    __syncthreads();
    if (threadIdx.x == 0) {
        __threadfence();
        atomicAdd(&g_arrive, 1u);
        unsigned v;
        do {
            asm volatile("ld.acquire.gpu.u32 %0, [%1];"
                         : "=r"(v) : "l"(&g_arrive) : "memory");
            if (v < target) __nanosleep(20);
        } while (v < target);
    }
    __syncthreads();
}

// ---------------------------------------------------------------------------
// Kernel 1: h_in = concat(x, emb_table[node_type_ids])
// ---------------------------------------------------------------------------
__global__ void concat_kernel(const float* __restrict__ x,
                              const int* __restrict__ types,
                              const float* __restrict__ emb, int N) {
    int i = blockIdx.x * blockDim.x + threadIdx.x;
    if (i >= N * 40) return;
    int n = i / 40;
    int q = i - n * 40;
    float4 v;
    if (q < 32) {
        v = ((const float4*)x)[n * 32 + q];
    } else {
        int tp = types[n];
        v = ((const float4*)emb)[tp * 8 + (q - 32)];
    }
    ((float4*)g_hin)[i] = v;
}

// ---------------------------------------------------------------------------
// Kernel 2 (tensor-core): g_gall = g_hin @ W_ih^T + (b_ih+b_hh), permuted cols
// ---------------------------------------------------------------------------
__global__ __launch_bounds__(256) void tc_pre(const float* __restrict__ Wih,
                                              const float* __restrict__ bih,
                                              const float* __restrict__ bhh, int N) {
    extern __shared__ float sm[];
    uint*  Wu  = (uint*)sm;
    float* Gsh = sm + G_OFF;
    __shared__ float bsh[CG];

    int t = threadIdx.x, lane = t & 31, warp = t >> 5;
    int wm = warp & 3, wn = warp >> 2;
    int cg = blockIdx.x, mt = blockIdx.y;
    int node0 = mt * MT;

    if (t < CG) {
        int wrow = (t & 3) * KD + cg * HS + (t >> 2);
        bsh[t] = bih[wrow] + bhh[wrow];
    }
    for (int idx = t; idx < CG * 40; idx += 256) {
        int row = idx / 40, f4 = idx % 40;
        int wrow = (row & 3) * KD + cg * HS + (row >> 2);
        float4 v = *(const float4*)(Wih + (size_t)wrow * KD + f4 * 4);
        uint* wp = Wu + row * 164 + f4 * 4;
        wp[0] = tf32c(v.x); wp[1] = tf32c(v.y); wp[2] = tf32c(v.z); wp[3] = tf32c(v.w);
    }
    __syncthreads();

    float d[4][4];
#pragma unroll
    for (int i = 0; i < 4; i++)
#pragma unroll
        for (int j = 0; j < 4; j++) d[i][j] = 0.f;

    int r0 = node0 + wm * 16 + (lane >> 2);
    int r1 = r0 + 8;
    if (r0 >= N) r0 = N - 1;
    if (r1 >= N) r1 = N - 1;
    const float* Ap0 = g_hin + (size_t)r0 * KD + (lane & 3);
    const float* Ap1 = g_hin + (size_t)r1 * KD + (lane & 3);
    uint a0 = tf32c(Ap0[0]), a2 = tf32c(Ap0[4]);
    uint a1 = tf32c(Ap1[0]), a3 = tf32c(Ap1[4]);
    const uint* Wb = Wu + (size_t)(wn * 32 + (lane >> 2)) * 164 + (lane & 3);

    for (int ks = 0; ks < 20; ks++) {
        int k = ks * 8;
        uint n0 = 0, n1 = 0, n2 = 0, n3 = 0;
        if (ks < 19) {
            n0 = tf32c(Ap0[k + 8]); n2 = tf32c(Ap0[k + 12]);
            n1 = tf32c(Ap1[k + 8]); n3 = tf32c(Ap1[k + 12]);
        }
#pragma unroll
        for (int t8 = 0; t8 < 4; t8++) {
            const uint* wp = Wb + t8 * 8 * 164 + k;
            mma8(d[t8][0], d[t8][1], d[t8][2], d[t8][3],
                 a0, a1, a2, a3, wp[0], wp[4]);
        }
        a0 = n0; a1 = n1; a2 = n2; a3 = n3;
    }

#pragma unroll
    for (int t8 = 0; t8 < 4; t8++) {
        int cb = wn * 32 + t8 * 8 + (lane & 3) * 2;
        int rr = wm * 16 + (lane >> 2);
        Gsh[rr * 68 + cb]           = d[t8][0] + bsh[cb];
        Gsh[rr * 68 + cb + 1]       = d[t8][1] + bsh[cb + 1];
        Gsh[(rr + 8) * 68 + cb]     = d[t8][2] + bsh[cb];
        Gsh[(rr + 8) * 68 + cb + 1] = d[t8][3] + bsh[cb + 1];
    }
    __syncthreads();
    {
        int i = t >> 2, q = t & 3;
        int nd = node0 + i;
        if (nd < N) {
            float* op = g_gall + (size_t)nd * G4 + cg * CG + q * 16;
            const float* sp = Gsh + i * 68 + q * 16;
#pragma unroll
            for (int j = 0; j < 4; j++)
                *(float4*)(op + j * 4) = *(const float4*)(sp + j * 4);
        }
    }
}

// ---------------------------------------------------------------------------
// Kernel 3 (persistent): all 16 LSTM steps in one launch.
// CTA owns col-group cg = bid%10, mt-slots {slot, slot+29, ...}.
// W_hh slice resident in SMEM (tf32) for entire kernel. Gathers double-
// buffered via cp.async, pipelined across tiles AND steps (gather is h-indep).
// Software grid barrier between steps (h is the only cross-CTA dependency).
// h stored tf32-rounded so A-operands load as raw bits (no cvt in hot loop).
// ---------------------------------------------------------------------------
__global__ __launch_bounds__(256, 2) void lstm_persist(const float* __restrict__ Whh,
                                                       const int* __restrict__ src,
                                                       int N) {
    extern __shared__ float sm[];
    uint*  Wu = (uint*)sm;
    float* G0 = sm + G_OFF;
    float* G1 = G0 + GBUF;
    uint g0a = (uint)__cvta_generic_to_shared(G0);
    uint g1a = (uint)__cvta_generic_to_shared(G1);

    int t = threadIdx.x, lane = t & 31, warp = t >> 5;
    int wm = warp & 3, wn = warp >> 2;
    int cg   = blockIdx.x % NCG;
    int slot = blockIdx.x / NCG;
    int MTL = (N + MT - 1) / MT;
    int nt = (MTL - 1 - slot) / SLOTS + 1;

    // epilogue thread mapping (fixed)
    int pr   = lane & 1;
    int nloc = wm * 16 + (lane >> 2) + pr * 8;
    int hlb  = wn * 8 + ((lane >> 1) & 1);

    // gather staging mapping (fixed)
    int si = t >> 2, sq = t & 3;

    // load W_hh col-group slice to SMEM as tf32 bits (once)
    for (int idx = t; idx < CG * 40; idx += 256) {
        int row = idx / 40, f4 = idx % 40;
        int wrow = (row & 3) * KD + cg * HS + (row >> 2);
        float4 v = *(const float4*)(Whh + (size_t)wrow * KD + f4 * 4);
        uint* wp = Wu + row * 164 + f4 * 4;
        wp[0] = tf32c(v.x); wp[1] = tf32c(v.y); wp[2] = tf32c(v.z); wp[3] = tf32c(v.w);
    }
    const uint* Wb = Wu + (size_t)(wn * 32 + (lane >> 2)) * 164 + (lane & 3);

    // prologue: prefetch gathers for pipeline slots p=0 (step0,ti0), p=1 (step0,ti1)
    {
        int nd = slot * MT + si;
        int sid = (nd < N) ? __ldg(&src[nd * DEG + 0]) : 0;
        const float* gp = g_gall + (size_t)sid * G4 + cg * CG + sq * 16;
        uint dst = g0a + (uint)(si * 68 + sq * 16) * 4;
        CP16(dst, gp); CP16(dst + 16, gp + 4); CP16(dst + 32, gp + 8); CP16(dst + 48, gp + 12);
        CPCOMMIT();
        nd = (slot + SLOTS) * MT + si;
        sid = (nd < N) ? __ldg(&src[nd * DEG + 0]) : 0;
        gp = g_gall + (size_t)sid * G4 + cg * CG + sq * 16;
        dst = g1a + (uint)(si * 68 + sq * 16) * 4;
        CP16(dst, gp); CP16(dst + 16, gp + 4); CP16(dst + 32, gp + 8); CP16(dst + 48, gp + 12);
        CPCOMMIT();
    }
    __syncthreads();   // W visible

    int p = 0;
    int pf_step = 0, pf_ti = 2;          // coordinates of pipeline slot p+2
    if (pf_ti >= nt) { pf_ti -= nt; pf_step++; }

    for (int step = 0; step < DEG; step++) {
        const float* hr = (step & 1) ? g_h1 : g_h0;
        float*       hw = (step & 1) ? g_h0 : g_h1;
        int first = (step == 0);

        for (int ti = 0; ti < nt; ti++, p++) {
            int node0 = (slot + ti * SLOTS) * MT;
            float* Gsh = (p & 1) ? G1 : G0;
            uint   gba = (p & 1) ? g1a : g0a;

            CPWAIT1();
            __syncthreads();   // staged gates for this tile visible

            // preload c (owner-only) — 4 scalars per thread
            int nd2 = node0 + nloc;
            bool val2 = nd2 < N;
            float cold[4] = {0.f, 0.f, 0.f, 0.f};
            if (!first && val2) {
                const float* cp = g_c + (size_t)nd2 * KD + cg * HS + hlb;
                cold[0] = cp[0]; cold[1] = cp[2]; cold[2] = cp[4]; cold[3] = cp[6];
            }

            float d[4][4];
#pragma unroll
            for (int i = 0; i < 4; i++)
#pragma unroll
                for (int j = 0; j < 4; j++) d[i][j] = 0.f;

            if (!first) {
                int r0 = node0 + wm * 16 + (lane >> 2);
                int r1 = r0 + 8;
                if (r0 >= N) r0 = N - 1;
                if (r1 >= N) r1 = N - 1;
                const uint* Ap0 = (const uint*)hr + (size_t)r0 * KD + (lane & 3);
                const uint* Ap1 = (const uint*)hr + (size_t)r1 * KD + (lane & 3);
                uint a0 = Ap0[0], a2 = Ap0[4];
                uint a1 = Ap1[0], a3 = Ap1[4];

                for (int ks = 0; ks < 20; ks++) {
                    int k = ks * 8;
                    uint n0 = 0, n1 = 0, n2 = 0, n3 = 0;
                    if (ks < 19) {
                        n0 = Ap0[k + 8]; n2 = Ap0[k + 12];
                        n1 = Ap1[k + 8]; n3 = Ap1[k + 12];
                    }
#pragma unroll
                    for (int t8 = 0; t8 < 4; t8++) {
                        const uint* wp = Wb + t8 * 8 * 164 + k;
                        mma8(d[t8][0], d[t8][1], d[t8][2], d[t8][3],
                             a0, a1, a2, a3, wp[0], wp[4]);
                    }
                    a0 = n0; a1 = n1; a2 = n2; a3 = n3;
                }
            }

            // epilogue: exchange so each thread owns (i,f,g,o); direct stores
            float* cwp = g_c + (size_t)nd2 * KD + cg * HS + hlb;
            float* hwp = hw  + (size_t)nd2 * KD + cg * HS + hlb;
#pragma unroll
            for (int t8 = 0; t8 < 4; t8++) {
                float v0 = pr ? d[t8][0] : d[t8][2];
                float v1 = pr ? d[t8][1] : d[t8][3];
                v0 = __shfl_xor_sync(0xffffffffu, v0, 1);
                v1 = __shfl_xor_sync(0xffffffffu, v1, 1);
                float gi, gf, gg, go;
                if (pr) { gi = v0;       gf = v1;       gg = d[t8][2]; go = d[t8][3]; }
                else    { gi = d[t8][0]; gf = d[t8][1]; gg = v0;       go = v1;       }
                int hl = hlb + t8 * 2;
                float4 gv = *(const float4*)(Gsh + nloc * 68 + hl * 4);
                gi += gv.x; gf += gv.y; gg += gv.z; go += gv.w;
                float cn = sigm(gf) * cold[t8] + sigm(gi) * tanhfast(gg);
                float hn = sigm(go) * tanhfast(cn);
                if (val2) {
                    cwp[t8 * 2] = cn;
                    hwp[t8 * 2] = __uint_as_float(tf32c(hn));
                }
            }
            __syncthreads();   // all Gsh reads done before reissuing into buffer

            // prefetch pipeline slot p+2 into the just-freed buffer
            if (pf_step < DEG) {
                int nd = (slot + pf_ti * SLOTS) * MT + si;
                int sid = (nd < N) ? __ldg(&src[nd * DEG + pf_step]) : 0;
                const float* gp = g_gall + (size_t)sid * G4 + cg * CG + sq * 16;
                uint dst = gba + (uint)(si * 68 + sq * 16) * 4;
                CP16(dst, gp); CP16(dst + 16, gp + 4);
                CP16(dst + 32, gp + 8); CP16(dst + 48, gp + 12);
            }
            CPCOMMIT();        // empty group when no prefetch (keeps invariant)
            pf_ti++;
            if (pf_ti >= nt) { pf_ti = 0; pf_step++; }
        }

        if (step < DEG - 1) grid_barrier((unsigned)(step + 1) * GRID);
    }
}

// ---------------------------------------------------------------------------
// Kernel 4: FFMA2 GEMM, Nc=128.
//   mode 1: g_rout = g_hin @ W_r^T + b_l
//   mode 2: out    = relu(g_h0 @ W_l^T + g_rout)
// ---------------------------------------------------------------------------
__global__ void gemm_kernel(const float* __restrict__ B,
                            const float* __restrict__ biasp,
                            float* __restrict__ Cext, int N, int mode) {
    __shared__ float As[16][64];
    __shared__ float Bs[16][64];
    const float* A = (mode == 1) ? g_hin : g_h0;
    float* C = (mode == 1) ? g_rout : Cext;

    int m0 = blockIdx.y * 64;
    int n0 = blockIdx.x * 64;
    int t  = threadIdx.x;
    int lr = t >> 2, lq = t & 3;
    int tx = t & 15, ty = t >> 4;

    ull acc[4][2];
#pragma unroll
    for (int i = 0; i < 4; i++) { acc[i][0] = 0ull; acc[i][1] = 0ull; }

    for (int kc = 0; kc < FDIM; kc += 16) {
        float4 av = make_float4(0.f, 0.f, 0.f, 0.f);
        int am = m0 + lr;
        if (am < N) av = *(const float4*)(A + (size_t)am * FDIM + kc + lq * 4);
        As[lq * 4 + 0][lr] = av.x; As[lq * 4 + 1][lr] = av.y;
        As[lq * 4 + 2][lr] = av.z; As[lq * 4 + 3][lr] = av.w;

        float4 bv = *(const float4*)(B + (size_t)(n0 + lr) * FDIM + kc + lq * 4);
        Bs[lq * 4 + 0][lr] = bv.x; Bs[lq * 4 + 1][lr] = bv.y;
        Bs[lq * 4 + 2][lr] = bv.z; Bs[lq * 4 + 3][lr] = bv.w;
        __syncthreads();

#pragma unroll
        for (int kk = 0; kk < 16; kk++) {
            float4 a4 = *(const float4*)&As[kk][ty * 4];
            longlong2 b2 = *(const longlong2*)&Bs[kk][tx * 4];
            ull bx = (ull)b2.x, by = (ull)b2.y;
            float a[4] = {a4.x, a4.y, a4.z, a4.w};
#pragma unroll
            for (int i = 0; i < 4; i++) {
                ull a2 = dup2(a[i]);
                acc[i][0] = ffma2(a2, bx, acc[i][0]);
                acc[i][1] = ffma2(a2, by, acc[i][1]);
            }
        }
        __syncthreads();
    }

#pragma unroll
    for (int i = 0; i < 4; i++) {
        int m = m0 + ty * 4 + i;
        if (m < N) {
            float2 lo = unpk(acc[i][0]);
            float2 hi = unpk(acc[i][1]);
            float4 o;
            if (mode == 1) {
                float4 bb = *(const float4*)(biasp + n0 + tx * 4);
                o.x = lo.x + bb.x; o.y = lo.y + bb.y;
                o.z = hi.x + bb.z; o.w = hi.y + bb.w;
            } else {
                float4 rv = *(const float4*)(g_rout + (size_t)m * OUTC + n0 + tx * 4);
                o.x = fmaxf(lo.x + rv.x, 0.f);
                o.y = fmaxf(lo.y + rv.y, 0.f);
                o.z = fmaxf(hi.x + rv.z, 0.f);
                o.w = fmaxf(hi.y + rv.w, 0.f);
            }
            *(float4*)(C + (size_t)m * OUTC + n0 + tx * 4) = o;
        }
    }
}

// ---------------------------------------------------------------------------
// Launcher (graph-capturable: kernel launches only)
// ---------------------------------------------------------------------------
extern "C" void kernel_launch(void* const* d_in, const int* in_sizes, int n_in,
                              void* d_out, int out_size) {
    const float* x     = (const float*)d_in[0];
    const int*   types = (const int*)d_in[1];
    const int*   eidx  = (const int*)d_in[2];   // [2, E]: first E entries = src
    const float* emb   = (const float*)d_in[3];
    const float* W_ih  = (const float*)d_in[4];
    const float* W_hh  = (const float*)d_in[5];
    const float* b_ih  = (const float*)d_in[6];
    const float* b_hh  = (const float*)d_in[7];
    const float* W_l   = (const float*)d_in[8];
    const float* b_l   = (const float*)d_in[9];
    const float* W_r   = (const float*)d_in[10];
    float* out = (float*)d_out;

    int N = in_sizes[1];                 // = 50000
    const int* srcp = eidx;

    cudaFuncSetAttribute((const void*)tc_pre,
                         cudaFuncAttributeMaxDynamicSharedMemorySize, PRE_SMEM);
    cudaFuncSetAttribute((const void*)lstm_persist,
                         cudaFuncAttributeMaxDynamicSharedMemorySize, PERSIST_SMEM);

    reset_kernel<<<1, 1>>>();
    concat_kernel<<<(N * 40 + 255) / 256, 256>>>(x, types, emb, N);

    dim3 gtc(NCG, (N + MT - 1) / MT);
    tc_pre<<<gtc, 256, PRE_SMEM>>>(W_ih, b_ih, b_hh, N);

    dim3 g2(2, (N + 63) / 64);
    gemm_kernel<<<g2, 256>>>(W_r, b_l, nullptr, N, 1);

    lstm_persist<<<GRID, 256, PERSIST_SMEM>>>(W_hh, srcp, N);

    gemm_kernel<<<g2, 256>>>(W_l, nullptr, out, N, 2);
}

// round 12
// speedup vs baseline: 1.5329x; 1.5329x over previous
#include <cuda_runtime.h>
#include <cuda_fp16.h>
#include <math.h>

// Problem constants (fixed by the dataset)
#define NN    50000
#define FDIM  160
#define KD    160
#define G4    640
#define DEG   16
#define OUTC  128
#define HS    16              // hidden units per col-group
#define CG    64              // cols per col-group (HS hidden x 4 gates)
#define NCG   10              // col groups (160 / HS)
#define MT    64              // M tile (nodes per tile)
#define SLOTS 29              // mt-slots per col group
#define GRID  (NCG * SLOTS)   // 290 persistent CTAs (2/SM guaranteed resident)

typedef unsigned long long ull;
typedef unsigned int uint;

// Scratch (device globals — no runtime allocation allowed)
__device__ float g_hin  [(size_t)NN * FDIM];  // concat(x, emb) fp32; later holds fp32 h_last
__device__ uint  g_hin16[(size_t)NN * 80];    // concat fp16 (80 uints = 160 halves / row)
__device__ float g_gall [(size_t)NN * G4];    // permuted (hidden*4+gate) input gates fp32
__device__ float g_rout [(size_t)NN * OUTC];  // h_in@W_r^T + b_l
__device__ uint  g_ha   [(size_t)NN * 80];    // h ping (fp16 pairs)
__device__ uint  g_hb   [(size_t)NN * 80];    // h pong (fp16 pairs)
__device__ float g_c    [(size_t)NN * FDIM];  // cell state (fp32)
__device__ unsigned g_arrive;                 // grid-barrier counter

// ---------------------------------------------------------------------------
// helpers
// ---------------------------------------------------------------------------
__device__ __forceinline__ void mma16(float& d0, float& d1, float& d2, float& d3,
                                      uint a0, uint a1, uint a2, uint a3,
                                      uint b0, uint b1) {
    asm volatile("mma.sync.aligned.m16n8k16.row.col.f32.f16.f16.f32 "
                 "{%0,%1,%2,%3},{%4,%5,%6,%7},{%8,%9},{%0,%1,%2,%3};"
                 : "+f"(d0), "+f"(d1), "+f"(d2), "+f"(d3)
                 : "r"(a0), "r"(a1), "r"(a2), "r"(a3), "r"(b0), "r"(b1));
}
__device__ __forceinline__ ull ffma2(ull a, ull b, ull c) {
    ull d; asm("fma.rn.f32x2 %0, %1, %2, %3;" : "=l"(d) : "l"(a), "l"(b), "l"(c));
    return d;
}
__device__ __forceinline__ ull dup2(float x) {
    ull r; asm("mov.b64 %0, {%1, %1};" : "=l"(r) : "f"(x)); return r;
}
__device__ __forceinline__ float2 unpk(ull v) {
    float2 r; asm("mov.b64 {%0, %1}, %2;" : "=f"(r.x), "=f"(r.y) : "l"(v)); return r;
}
__device__ __forceinline__ float sigm(float x)     { return 1.f / (1.f + __expf(-x)); }
__device__ __forceinline__ float tanhfast(float x) { return 1.f - 2.f / (1.f + __expf(2.f * x)); }

#define CP16(dst, src) asm volatile("cp.async.cg.shared.global [%0], [%1], 16;" \
                                    :: "r"(dst), "l"(src))
#define CPCOMMIT() asm volatile("cp.async.commit_group;" ::: "memory")
#define CPWAIT1()  asm volatile("cp.async.wait_group 1;" ::: "memory")

// SMEM layouts (bytes)
#define W16_BYTES (CG * 168 * 2)                  // 21504: fp16 W slice, 168-half rows
#define GBUF_BYTES (64 * 68 * 4)                  // 17408: staged fp32 gates
#define PERSIST_SMEM (W16_BYTES + 2 * GBUF_BYTES) // 56320 -> 2 CTAs/SM easily
#define PRE_SMEM     (W16_BYTES + GBUF_BYTES)     // 38912

// ---------------------------------------------------------------------------
// barrier reset
// ---------------------------------------------------------------------------
__global__ void reset_kernel() { g_arrive = 0u; }

__device__ __forceinline__ void grid_barrier(unsigned target) {
    __syncthreads();
    if (threadIdx.x == 0) {
        __threadfence();
        atomicAdd(&g_arrive, 1u);
        unsigned v;
        do {
            asm volatile("ld.acquire.gpu.u32 %0, [%1];"
                         : "=r"(v) : "l"(&g_arrive) : "memory");
            if (v < target) __nanosleep(20);
        } while (v < target);
    }
    __syncthreads();
}

// ---------------------------------------------------------------------------
// Kernel 1: h_in = concat(x, emb) -> fp32 + fp16 copies
// ---------------------------------------------------------------------------
__global__ void concat_kernel(const float* __restrict__ x,
                              const int* __restrict__ types,
                              const float* __restrict__ emb, int N) {
    int i = blockIdx.x * blockDim.x + threadIdx.x;   // float4 index over N*40
    if (i >= N * 40) return;
    int n = i / 40;
    int q = i - n * 40;
    float4 v;
    if (q < 32) {
        v = ((const float4*)x)[n * 32 + q];
    } else {
        int tp = types[n];
        v = ((const float4*)emb)[tp * 8 + (q - 32)];
    }
    ((float4*)g_hin)[i] = v;
    __half2 p0 = __floats2half2_rn(v.x, v.y);
    __half2 p1 = __floats2half2_rn(v.z, v.w);
    uint2 u;
    u.x = *(uint*)&p0; u.y = *(uint*)&p1;
    ((uint2*)g_hin16)[i] = u;
}

// ---------------------------------------------------------------------------
// Kernel 2 (fp16 HMMA): g_gall = h_in @ W_ih^T + (b_ih+b_hh), permuted cols.
// CTA (cg, mt): M=64 nodes, N=64 permuted cols, K=160. 8 warps (4 m x 2 n).
// ---------------------------------------------------------------------------
__global__ __launch_bounds__(256) void tc_pre(const float* __restrict__ Wih,
                                              const float* __restrict__ bih,
                                              const float* __restrict__ bhh, int N) {
    extern __shared__ char smb[];
    __half* w16 = (__half*)smb;                  // [64][168] fp16
    float*  Gsh = (float*)(smb + W16_BYTES);     // [64][68]
    __shared__ float bsh[CG];

    int t = threadIdx.x, lane = t & 31, warp = t >> 5;
    int wm = warp & 3, wn = warp >> 2;
    int gr = lane >> 2, q = lane & 3;
    int cg = blockIdx.x, mt = blockIdx.y;
    int node0 = mt * MT;

    if (t < CG) {
        int wrow = (t & 3) * KD + cg * HS + (t >> 2);
        bsh[t] = bih[wrow] + bhh[wrow];
    }
    for (int idx = t; idx < CG * KD; idx += 256) {
        int row = idx / KD, k = idx - row * KD;
        int wrow = (row & 3) * KD + cg * HS + (row >> 2);
        w16[row * 168 + k] = __float2half_rn(Wih[(size_t)wrow * KD + k]);
    }
    __syncthreads();

    float d[4][4];
#pragma unroll
    for (int i = 0; i < 4; i++)
#pragma unroll
        for (int j = 0; j < 4; j++) d[i][j] = 0.f;

    int r0 = node0 + wm * 16 + gr;
    int r1 = r0 + 8;
    if (r0 >= N) r0 = N - 1;
    if (r1 >= N) r1 = N - 1;
    const uint* Ap0 = g_hin16 + (size_t)r0 * 80 + q;
    const uint* Ap1 = g_hin16 + (size_t)r1 * 80 + q;
    const uint* Wb  = (const uint*)w16 + (size_t)(wn * 32 + gr) * 84 + q;

#pragma unroll
    for (int ks = 0; ks < 10; ks++) {
        uint a0 = Ap0[ks * 8],     a1 = Ap1[ks * 8];
        uint a2 = Ap0[ks * 8 + 4], a3 = Ap1[ks * 8 + 4];
#pragma unroll
        for (int t8 = 0; t8 < 4; t8++) {
            const uint* wp = Wb + t8 * 672 + ks * 8;   // 8 rows * 84 uints
            mma16(d[t8][0], d[t8][1], d[t8][2], d[t8][3],
                  a0, a1, a2, a3, wp[0], wp[4]);
        }
    }

#pragma unroll
    for (int t8 = 0; t8 < 4; t8++) {
        int cb = wn * 32 + t8 * 8 + q * 2;
        int rr = wm * 16 + gr;
        Gsh[rr * 68 + cb]           = d[t8][0] + bsh[cb];
        Gsh[rr * 68 + cb + 1]       = d[t8][1] + bsh[cb + 1];
        Gsh[(rr + 8) * 68 + cb]     = d[t8][2] + bsh[cb];
        Gsh[(rr + 8) * 68 + cb + 1] = d[t8][3] + bsh[cb + 1];
    }
    __syncthreads();
    {
        int i = t >> 2, qq = t & 3;
        int nd = node0 + i;
        if (nd < N) {
            float* op = g_gall + (size_t)nd * G4 + cg * CG + qq * 16;
            const float* sp = Gsh + i * 68 + qq * 16;
#pragma unroll
            for (int j = 0; j < 4; j++)
                *(float4*)(op + j * 4) = *(const float4*)(sp + j * 4);
        }
    }
}

// ---------------------------------------------------------------------------
// Kernel 3 (persistent, fp16 HMMA): all 16 LSTM steps.
// W_hh slice fp16-resident in SMEM; gathers cp.async double-buffered across
// tiles and steps; grid barrier between steps; h stored fp16, last-step h
// additionally written fp32 into g_hin for the final SAGE gemm.
// ---------------------------------------------------------------------------
__global__ __launch_bounds__(256, 2) void lstm_persist(const float* __restrict__ Whh,
                                                       const int* __restrict__ src,
                                                       int N) {
    extern __shared__ char smb[];
    __half* w16 = (__half*)smb;
    float* G0 = (float*)(smb + W16_BYTES);
    float* G1 = (float*)(smb + W16_BYTES + GBUF_BYTES);
    uint g0a = (uint)__cvta_generic_to_shared(G0);
    uint g1a = (uint)__cvta_generic_to_shared(G1);

    int t = threadIdx.x, lane = t & 31, warp = t >> 5;
    int wm = warp & 3, wn = warp >> 2;
    int gr = lane >> 2, q = lane & 3;
    int cg   = blockIdx.x % NCG;
    int slot = blockIdx.x / NCG;
    int MTL = (N + MT - 1) / MT;
    int nt = (MTL - 1 - slot) / SLOTS + 1;

    // epilogue thread mapping (fixed)
    int pr   = lane & 1;
    int nloc = wm * 16 + gr + pr * 8;
    int hlb  = wn * 8 + ((lane >> 1) & 1);

    // gather staging mapping (fixed)
    int si = t >> 2, sq = t & 3;

    // load W_hh col-group slice to SMEM as fp16 (once)
    for (int idx = t; idx < CG * KD; idx += 256) {
        int row = idx / KD, k = idx - row * KD;
        int wrow = (row & 3) * KD + cg * HS + (row >> 2);
        w16[row * 168 + k] = __float2half_rn(Whh[(size_t)wrow * KD + k]);
    }
    const uint* Wb = (const uint*)w16 + (size_t)(wn * 32 + gr) * 84 + q;

    // prologue: prefetch gathers for pipeline slots p=0,1 (step 0, ti 0/1)
    {
        int nd = slot * MT + si;
        int sid = (nd < N) ? __ldg(&src[nd * DEG + 0]) : 0;
        const float* gp = g_gall + (size_t)sid * G4 + cg * CG + sq * 16;
        uint dst = g0a + (uint)(si * 68 + sq * 16) * 4;
        CP16(dst, gp); CP16(dst + 16, gp + 4); CP16(dst + 32, gp + 8); CP16(dst + 48, gp + 12);
        CPCOMMIT();
        nd = (slot + SLOTS) * MT + si;
        sid = (nd < N) ? __ldg(&src[nd * DEG + 0]) : 0;
        gp = g_gall + (size_t)sid * G4 + cg * CG + sq * 16;
        dst = g1a + (uint)(si * 68 + sq * 16) * 4;
        CP16(dst, gp); CP16(dst + 16, gp + 4); CP16(dst + 32, gp + 8); CP16(dst + 48, gp + 12);
        CPCOMMIT();
    }
    __syncthreads();   // W visible

    int p = 0;
    int pf_step = 0, pf_ti = 2;
    if (pf_ti >= nt) { pf_ti -= nt; pf_step++; }

    for (int step = 0; step < DEG; step++) {
        const uint* h16r = (step & 1) ? g_hb : g_ha;
        uint*       h16w = (step & 1) ? g_ha : g_hb;
        int first = (step == 0);
        int last  = (step == DEG - 1);

        for (int ti = 0; ti < nt; ti++, p++) {
            int node0 = (slot + ti * SLOTS) * MT;
            float* Gsh = (p & 1) ? G1 : G0;
            uint   gba = (p & 1) ? g1a : g0a;

            CPWAIT1();
            __syncthreads();   // staged gates visible

            int nd2 = node0 + nloc;
            bool val2 = nd2 < N;
            float cold[4] = {0.f, 0.f, 0.f, 0.f};
            if (!first && val2) {
                const float* cp = g_c + (size_t)nd2 * KD + cg * HS + hlb;
                cold[0] = cp[0]; cold[1] = cp[2]; cold[2] = cp[4]; cold[3] = cp[6];
            }

            float d[4][4];
#pragma unroll
            for (int i = 0; i < 4; i++)
#pragma unroll
                for (int j = 0; j < 4; j++) d[i][j] = 0.f;

            if (!first) {
                int r0 = node0 + wm * 16 + gr;
                int r1 = r0 + 8;
                if (r0 >= N) r0 = N - 1;
                if (r1 >= N) r1 = N - 1;
                const uint* Ap0 = h16r + (size_t)r0 * 80 + q;
                const uint* Ap1 = h16r + (size_t)r1 * 80 + q;
#pragma unroll
                for (int ks = 0; ks < 10; ks++) {
                    uint a0 = Ap0[ks * 8],     a1 = Ap1[ks * 8];
                    uint a2 = Ap0[ks * 8 + 4], a3 = Ap1[ks * 8 + 4];
#pragma unroll
                    for (int t8 = 0; t8 < 4; t8++) {
                        const uint* wp = Wb + t8 * 672 + ks * 8;
                        mma16(d[t8][0], d[t8][1], d[t8][2], d[t8][3],
                              a0, a1, a2, a3, wp[0], wp[4]);
                    }
                }
            }

            // epilogue: pair exchange -> each thread owns (i,f,g,o)
            float* cwp = g_c + (size_t)nd2 * KD + cg * HS + hlb;
            __half* hwp = (__half*)h16w + (size_t)nd2 * KD + cg * HS + hlb;
            float* hfp = g_hin + (size_t)nd2 * FDIM + cg * HS + hlb;
#pragma unroll
            for (int t8 = 0; t8 < 4; t8++) {
                float v0 = pr ? d[t8][0] : d[t8][2];
                float v1 = pr ? d[t8][1] : d[t8][3];
                v0 = __shfl_xor_sync(0xffffffffu, v0, 1);
                v1 = __shfl_xor_sync(0xffffffffu, v1, 1);
                float gi, gf, gg, go;
                if (pr) { gi = v0;       gf = v1;       gg = d[t8][2]; go = d[t8][3]; }
                else    { gi = d[t8][0]; gf = d[t8][1]; gg = v0;       go = v1;       }
                int hl = hlb + t8 * 2;
                float4 gv = *(const float4*)(Gsh + nloc * 68 + hl * 4);
                gi += gv.x; gf += gv.y; gg += gv.z; go += gv.w;
                float cn = sigm(gf) * cold[t8] + sigm(gi) * tanhfast(gg);
                float hn = sigm(go) * tanhfast(cn);
                if (val2) {
                    cwp[t8 * 2] = cn;
                    hwp[t8 * 2] = __float2half_rn(hn);
                    if (last) hfp[t8 * 2] = hn;
                }
            }
            __syncthreads();   // all Gsh reads done before refilling buffer

            // prefetch pipeline slot p+2
            if (pf_step < DEG) {
                int nd = (slot + pf_ti * SLOTS) * MT + si;
                int sid = (nd < N) ? __ldg(&src[nd * DEG + pf_step]) : 0;
                const float* gp = g_gall + (size_t)sid * G4 + cg * CG + sq * 16;
                uint dst = gba + (uint)(si * 68 + sq * 16) * 4;
                CP16(dst, gp); CP16(dst + 16, gp + 4);
                CP16(dst + 32, gp + 8); CP16(dst + 48, gp + 12);
            }
            CPCOMMIT();
            pf_ti++;
            if (pf_ti >= nt) { pf_ti = 0; pf_step++; }
        }

        if (step < DEG - 1) grid_barrier((unsigned)(step + 1) * GRID);
    }
}

// ---------------------------------------------------------------------------
// Kernel 4: FFMA2 GEMM, Nc=128.
//   mode 1: g_rout = g_hin @ W_r^T + b_l          (g_hin = concat output)
//   mode 2: out    = relu(g_hin @ W_l^T + g_rout) (g_hin = fp32 h_last)
// ---------------------------------------------------------------------------
__global__ void gemm_kernel(const float* __restrict__ B,
                            const float* __restrict__ biasp,
                            float* __restrict__ Cext, int N, int mode) {
    __shared__ float As[16][64];
    __shared__ float Bs[16][64];
    const float* A = g_hin;
    float* C = (mode == 1) ? g_rout : Cext;

    int m0 = blockIdx.y * 64;
    int n0 = blockIdx.x * 64;
    int t  = threadIdx.x;
    int lr = t >> 2, lq = t & 3;
    int tx = t & 15, ty = t >> 4;

    ull acc[4][2];
#pragma unroll
    for (int i = 0; i < 4; i++) { acc[i][0] = 0ull; acc[i][1] = 0ull; }

    for (int kc = 0; kc < FDIM; kc += 16) {
        float4 av = make_float4(0.f, 0.f, 0.f, 0.f);
        int am = m0 + lr;
        if (am < N) av = *(const float4*)(A + (size_t)am * FDIM + kc + lq * 4);
        As[lq * 4 + 0][lr] = av.x; As[lq * 4 + 1][lr] = av.y;
        As[lq * 4 + 2][lr] = av.z; As[lq * 4 + 3][lr] = av.w;

        float4 bv = *(const float4*)(B + (size_t)(n0 + lr) * FDIM + kc + lq * 4);
        Bs[lq * 4 + 0][lr] = bv.x; Bs[lq * 4 + 1][lr] = bv.y;
        Bs[lq * 4 + 2][lr] = bv.z; Bs[lq * 4 + 3][lr] = bv.w;
        __syncthreads();

#pragma unroll
        for (int kk = 0; kk < 16; kk++) {
            float4 a4 = *(const float4*)&As[kk][ty * 4];
            longlong2 b2 = *(const longlong2*)&Bs[kk][tx * 4];
            ull bx = (ull)b2.x, by = (ull)b2.y;
            float a[4] = {a4.x, a4.y, a4.z, a4.w};
#pragma unroll
            for (int i = 0; i < 4; i++) {
                ull a2 = dup2(a[i]);
                acc[i][0] = ffma2(a2, bx, acc[i][0]);
                acc[i][1] = ffma2(a2, by, acc[i][1]);
            }
        }
        __syncthreads();
    }

#pragma unroll
    for (int i = 0; i < 4; i++) {
        int m = m0 + ty * 4 + i;
        if (m < N) {
            float2 lo = unpk(acc[i][0]);
            float2 hi = unpk(acc[i][1]);
            float4 o;
            if (mode == 1) {
                float4 bb = *(const float4*)(biasp + n0 + tx * 4);
                o.x = lo.x + bb.x; o.y = lo.y + bb.y;
                o.z = hi.x + bb.z; o.w = hi.y + bb.w;
            } else {
                float4 rv = *(const float4*)(g_rout + (size_t)m * OUTC + n0 + tx * 4);
                o.x = fmaxf(lo.x + rv.x, 0.f);
                o.y = fmaxf(lo.y + rv.y, 0.f);
                o.z = fmaxf(hi.x + rv.z, 0.f);
                o.w = fmaxf(hi.y + rv.w, 0.f);
            }
            *(float4*)(C + (size_t)m * OUTC + n0 + tx * 4) = o;
        }
    }
}

// ---------------------------------------------------------------------------
// Launcher (graph-capturable: kernel launches only).
// Order chosen so ncu's skip-5 capture lands on lstm_persist (launch #6).
// ---------------------------------------------------------------------------
extern "C" void kernel_launch(void* const* d_in, const int* in_sizes, int n_in,
                              void* d_out, int out_size) {
    const float* x     = (const float*)d_in[0];
    const int*   types = (const int*)d_in[1];
    const int*   eidx  = (const int*)d_in[2];   // [2, E]: first E entries = src
    const float* emb   = (const float*)d_in[3];
    const float* W_ih  = (const float*)d_in[4];
    const float* W_hh  = (const float*)d_in[5];
    const float* b_ih  = (const float*)d_in[6];
    const float* b_hh  = (const float*)d_in[7];
    const float* W_l   = (const float*)d_in[8];
    const float* b_l   = (const float*)d_in[9];
    const float* W_r   = (const float*)d_in[10];
    float* out = (float*)d_out;

    int N = in_sizes[1];                 // = 50000
    const int* srcp = eidx;

    cudaFuncSetAttribute((const void*)tc_pre,
                         cudaFuncAttributeMaxDynamicSharedMemorySize, PRE_SMEM);
    cudaFuncSetAttribute((const void*)lstm_persist,
                         cudaFuncAttributeMaxDynamicSharedMemorySize, PERSIST_SMEM);

    concat_kernel<<<(N * 40 + 255) / 256, 256>>>(x, types, emb, N);   // 1

    dim3 gtc(NCG, (N + MT - 1) / MT);
    tc_pre<<<gtc, 256, PRE_SMEM>>>(W_ih, b_ih, b_hh, N);              // 2

    dim3 g2(2, (N + 63) / 64);
    gemm_kernel<<<g2, 256>>>(W_r, b_l, nullptr, N, 1);                // 3

    reset_kernel<<<1, 1>>>();                                         // 4
    reset_kernel<<<1, 1>>>();                                         // 5 (pad for ncu -s 5)

    lstm_persist<<<GRID, 256, PERSIST_SMEM>>>(W_hh, srcp, N);         // 6 <- profiled

    gemm_kernel<<<g2, 256>>>(W_l, nullptr, out, N, 2);                // 7
}

// round 14
// speedup vs baseline: 2.6339x; 1.7182x over previous
#include <cuda_runtime.h>
#include <cuda_fp16.h>
#include <math.h>

// Problem constants
#define NN    50000
#define FDIM  160
#define KD    160
#define DEG   16
#define OUTC  128
#define HS    16
#define CG    64
#define NCG   10
#define MT    64
#define SLOTS 29
#define GRID  (NCG * SLOTS)     // 290 persistent CTAs (2/SM resident)

typedef unsigned long long ull;
typedef unsigned int uint;

// Device-global scratch
__device__ float g_hin  [(size_t)NN * FDIM];  // concat fp32 (for gemm mode 1)
__device__ uint  g_hin16[(size_t)NN * 80];    // concat fp16 pairs
__device__ uint  g_g16  [(size_t)NN * 320];   // fp16 gates, permuted, 1280B/node
__device__ float g_rout [(size_t)NN * OUTC];
__device__ uint  g_ha   [(size_t)NN * 80];    // h ping fp16
__device__ uint  g_hb   [(size_t)NN * 80];    // h pong fp16
__device__ float g_c2   [(size_t)NCG * NN * HS]; // cell state, cg-permuted
__device__ unsigned g_arrive;

// helpers ------------------------------------------------------------------
__device__ __forceinline__ void mma16(float& d0, float& d1, float& d2, float& d3,
                                      uint a0, uint a1, uint a2, uint a3,
                                      uint b0, uint b1) {
    asm volatile("mma.sync.aligned.m16n8k16.row.col.f32.f16.f16.f32 "
                 "{%0,%1,%2,%3},{%4,%5,%6,%7},{%8,%9},{%0,%1,%2,%3};"
                 : "+f"(d0), "+f"(d1), "+f"(d2), "+f"(d3)
                 : "r"(a0), "r"(a1), "r"(a2), "r"(a3), "r"(b0), "r"(b1));
}
__device__ __forceinline__ void ldsm4(uint& r0, uint& r1, uint& r2, uint& r3, uint a) {
    asm volatile("ldmatrix.sync.aligned.m8n8.x4.shared.b16 {%0,%1,%2,%3}, [%4];"
                 : "=r"(r0), "=r"(r1), "=r"(r2), "=r"(r3) : "r"(a));
}
__device__ __forceinline__ ull ffma2(ull a, ull b, ull c) {
    ull d; asm("fma.rn.f32x2 %0, %1, %2, %3;" : "=l"(d) : "l"(a), "l"(b), "l"(c));
    return d;
}
__device__ __forceinline__ ull dup2(float x) {
    ull r; asm("mov.b64 %0, {%1, %1};" : "=l"(r) : "f"(x)); return r;
}
__device__ __forceinline__ float2 unpk(ull v) {
    float2 r; asm("mov.b64 {%0, %1}, %2;" : "=f"(r.x), "=f"(r.y) : "l"(v)); return r;
}
__device__ __forceinline__ float sigm(float x)     { return 1.f / (1.f + __expf(-x)); }
__device__ __forceinline__ float tanhfast(float x) { return 1.f - 2.f / (1.f + __expf(2.f * x)); }

#define CP16(dst, src) asm volatile("cp.async.cg.shared.global [%0], [%1], 16;" \
                                    :: "r"(dst), "l"(src))
#define CPCOMMIT() asm volatile("cp.async.commit_group;" ::: "memory")
#define CPWAIT1()  asm volatile("cp.async.wait_group 1;" ::: "memory")

// SMEM layouts (bytes). W rows: 64 x 336 (168 halves, conflict-free ldmatrix).
#define PW    0
#define PA0   21504
#define PA1   43008
#define PG0   64512
#define PG1   73728
#define PHST  82944
#define PERSIST_SMEM 86016   // + 3072 hst
#define QW    0
#define QA0   21504
#define QA1   43008
#define QGST  64512
#define PRE_SMEM 73728

// barrier ------------------------------------------------------------------
__global__ void reset_kernel() { g_arrive = 0u; }

__device__ __forceinline__ void grid_barrier(unsigned target) {
    __syncthreads();
    if (threadIdx.x == 0) {
        __threadfence();
        atomicAdd(&g_arrive, 1u);
        unsigned v;
        do {
            asm volatile("ld.acquire.gpu.u32 %0, [%1];"
                         : "=r"(v) : "l"(&g_arrive) : "memory");
            if (v < target) __nanosleep(20);
        } while (v < target);
    }
    __syncthreads();
}

// Kernel 1: concat ---------------------------------------------------------
__global__ void concat_kernel(const float* __restrict__ x,
                              const int* __restrict__ types,
                              const float* __restrict__ emb, int N) {
    int i = blockIdx.x * blockDim.x + threadIdx.x;
    if (i >= N * 40) return;
    int n = i / 40;
    int q = i - n * 40;
    float4 v;
    if (q < 32) v = ((const float4*)x)[n * 32 + q];
    else        v = ((const float4*)emb)[types[n] * 8 + (q - 32)];
    ((float4*)g_hin)[i] = v;
    __half2 p0 = __floats2half2_rn(v.x, v.y);
    __half2 p1 = __floats2half2_rn(v.z, v.w);
    uint2 u; u.x = *(uint*)&p0; u.y = *(uint*)&p1;
    ((uint2*)g_hin16)[i] = u;
}

// Kernel 2: tc_pre (persistent per col-group, cp.async A, ldmatrix) --------
__global__ __launch_bounds__(256, 2) void tc_pre(const float* __restrict__ Wih,
                                                 const float* __restrict__ bih,
                                                 const float* __restrict__ bhh, int N) {
    extern __shared__ char smb[];
    uint wsh = (uint)__cvta_generic_to_shared(smb);
    int t = threadIdx.x, lane = t & 31, warp = t >> 5;
    int wm = warp & 3, wn = warp >> 2;
    int cg = blockIdx.x % NCG, slot = blockIdx.x / NCG;
    int MTL = (N + MT - 1) / MT;
    int nt = (MTL - 1 - slot) / SLOTS + 1;

    __shared__ float bsh[CG];
    if (t < CG) {
        int wrow = (t & 3) * KD + cg * HS + (t >> 2);
        bsh[t] = bih[wrow] + bhh[wrow];
    }
    __half* w16 = (__half*)smb;
    for (int idx = t; idx < CG * KD; idx += 256) {
        int row = idx / KD, k = idx - row * KD;
        int wrow = (row & 3) * KD + cg * HS + (row >> 2);
        w16[row * 168 + k] = __float2half_rn(Wih[(size_t)wrow * KD + k]);
    }

    int lrow = lane & 7;
    uint aoff  = (uint)((wm * 16 + lrow + ((lane >> 3) & 1) * 8) * 336 + ((lane >> 4) & 1) * 16);
    uint boff0 = wsh + (uint)((wn * 32 + lrow + ((lane >> 4) & 1) * 8) * 336 + ((lane >> 3) & 1) * 16);
    uint boff1 = boff0 + 16 * 336;

    // prologue A prefetch for tiles 0,1
    for (int pi = 0; pi < 2; pi++) {
        if (pi < nt) {
            int node0 = (slot + pi * SLOTS) * MT;
            uint ab = wsh + QA0 + (uint)pi * 21504u;
#pragma unroll
            for (int j = 0; j < 5; j++) {
                int idx = t + 256 * j, row = idx / 20, ch = idx - row * 20;
                int nd = node0 + row; if (nd >= N) nd = N - 1;
                CP16(ab + (uint)(row * 336 + ch * 16),
                     (const char*)g_hin16 + (size_t)nd * 320 + ch * 16);
            }
        }
        CPCOMMIT();
    }

    for (int ti = 0; ti < nt; ti++) {
        int node0 = (slot + ti * SLOTS) * MT;
        uint ab = wsh + QA0 + (uint)(ti & 1) * 21504u;
        CPWAIT1();
        __syncthreads();

        float d[4][4];
#pragma unroll
        for (int i = 0; i < 4; i++)
#pragma unroll
            for (int j = 0; j < 4; j++) d[i][j] = 0.f;

#pragma unroll
        for (int ks = 0; ks < 10; ks++) {
            uint a0, a1, a2, a3, p0, p1, p2, p3, q0, q1, q2, q3;
            ldsm4(a0, a1, a2, a3, ab + aoff + ks * 32);
            ldsm4(p0, p1, p2, p3, boff0 + ks * 32);
            ldsm4(q0, q1, q2, q3, boff1 + ks * 32);
            mma16(d[0][0], d[0][1], d[0][2], d[0][3], a0, a1, a2, a3, p0, p1);
            mma16(d[1][0], d[1][1], d[1][2], d[1][3], a0, a1, a2, a3, p2, p3);
            mma16(d[2][0], d[2][1], d[2][2], d[2][3], a0, a1, a2, a3, q0, q1);
            mma16(d[3][0], d[3][1], d[3][2], d[3][3], a0, a1, a2, a3, q2, q3);
        }

        // epilogue: bias + fp16 stage
        {
            int gr = lane >> 2, q = lane & 3;
            int rr = wm * 16 + gr;
#pragma unroll
            for (int t8 = 0; t8 < 4; t8++) {
                int cb = wn * 32 + t8 * 8 + q * 2;
                float b0v = bsh[cb], b1v = bsh[cb + 1];
                *(__half2*)(smb + QGST + rr * 144 + cb * 2) =
                    __floats2half2_rn(d[t8][0] + b0v, d[t8][1] + b1v);
                *(__half2*)(smb + QGST + (rr + 8) * 144 + cb * 2) =
                    __floats2half2_rn(d[t8][2] + b0v, d[t8][3] + b1v);
            }
        }
        __syncthreads();   // all MMA reads of A buf done + stage complete

        // coalesced output (FULL 128B/row: 2 x uint4 per thread)
        {
            int row = t >> 2, piece = t & 3;
            int nd = node0 + row;
            if (nd < N) {
                char* dst = (char*)g_g16 + (size_t)nd * 1280 + cg * 128 + piece * 32;
                const char* sp = smb + QGST + row * 144 + piece * 32;
                *(uint4*)dst        = *(const uint4*)sp;
                *(uint4*)(dst + 16) = *(const uint4*)(sp + 16);
            }
        }
        // next A prefetch into the just-freed buffer
        if (ti + 2 < nt) {
            int n2 = (slot + (ti + 2) * SLOTS) * MT;
#pragma unroll
            for (int j = 0; j < 5; j++) {
                int idx = t + 256 * j, row = idx / 20, ch = idx - row * 20;
                int nd = n2 + row; if (nd >= N) nd = N - 1;
                CP16(ab + (uint)(row * 336 + ch * 16),
                     (const char*)g_hin16 + (size_t)nd * 320 + ch * 16);
            }
        }
        CPCOMMIT();
    }
}

// Kernel 3: persistent LSTM, cp.async-staged A + gathers, ldmatrix ---------
__global__ __launch_bounds__(256, 2) void lstm_persist(const float* __restrict__ Whh,
                                                       const int* __restrict__ src,
                                                       int N) {
    extern __shared__ char smb[];
    uint wsh = (uint)__cvta_generic_to_shared(smb);
    int t = threadIdx.x, lane = t & 31, warp = t >> 5;
    int wm = warp & 3, wn = warp >> 2;
    int cg = blockIdx.x % NCG, slot = blockIdx.x / NCG;
    int MTL = (N + MT - 1) / MT;
    int nt = (MTL - 1 - slot) / SLOTS + 1;

    int lrow = lane & 7;
    uint aoff  = (uint)((wm * 16 + lrow + ((lane >> 3) & 1) * 8) * 336 + ((lane >> 4) & 1) * 16);
    uint boff0 = wsh + (uint)((wn * 32 + lrow + ((lane >> 4) & 1) * 8) * 336 + ((lane >> 3) & 1) * 16);
    uint boff1 = boff0 + 16 * 336;
    int pr   = lane & 1;
    int nloc = wm * 16 + (lane >> 2) + pr * 8;
    int hlb  = wn * 8 + ((lane >> 1) & 1);
    int si = t >> 2, sq = t & 3;

    __half* w16 = (__half*)smb;
    for (int idx = t; idx < CG * KD; idx += 256) {
        int row = idx / KD, k = idx - row * KD;
        int wrow = (row & 3) * KD + cg * HS + (row >> 2);
        w16[row * 168 + k] = __float2half_rn(Whh[(size_t)wrow * KD + k]);
    }

    for (int step = 0; step < DEG; step++) {
        const uint* hr = (step & 1) ? g_hb : g_ha;
        uint*       hw = (step & 1) ? g_ha : g_hb;
        int first = (step == 0);

        // prologue prefetch tiles 0,1
        for (int pi = 0; pi < 2; pi++) {
            if (pi < nt) {
                int node0 = (slot + pi * SLOTS) * MT;
                if (!first) {
                    uint ab = wsh + PA0 + (uint)pi * 21504u;
#pragma unroll
                    for (int j = 0; j < 5; j++) {
                        int idx = t + 256 * j, row = idx / 20, ch = idx - row * 20;
                        int nd = node0 + row; if (nd >= N) nd = N - 1;
                        CP16(ab + (uint)(row * 336 + ch * 16),
                             (const char*)hr + (size_t)nd * 320 + ch * 16);
                    }
                }
                int nd = node0 + si;
                int sid = (nd < N) ? __ldg(&src[nd * DEG + step]) : 0;
                const char* gs = (const char*)g_g16 + (size_t)sid * 1280 + cg * 128 + sq * 32;
                uint gd = wsh + PG0 + (uint)(pi * 9216 + si * 144 + sq * 32);
                CP16(gd, gs); CP16(gd + 16, gs + 16);
            }
            CPCOMMIT();
        }

        for (int ti = 0; ti < nt; ti++) {
            int node0 = (slot + ti * SLOTS) * MT;
            uint ab = wsh + PA0 + (uint)(ti & 1) * 21504u;
            char* gsh = smb + PG0 + (ti & 1) * 9216;
            CPWAIT1();
            __syncthreads();

            int nd2 = node0 + nloc;
            bool val2 = nd2 < N;
            float* cbase = g_c2 + ((size_t)cg * NN + (val2 ? nd2 : 0)) * HS + hlb;
            float cold[4] = {0.f, 0.f, 0.f, 0.f};
            if (!first && val2) {
                cold[0] = cbase[0]; cold[1] = cbase[2];
                cold[2] = cbase[4]; cold[3] = cbase[6];
            }

            float d[4][4];
#pragma unroll
            for (int i = 0; i < 4; i++)
#pragma unroll
                for (int j = 0; j < 4; j++) d[i][j] = 0.f;

            if (!first) {
#pragma unroll
                for (int ks = 0; ks < 10; ks++) {
                    uint a0, a1, a2, a3, p0, p1, p2, p3, q0, q1, q2, q3;
                    ldsm4(a0, a1, a2, a3, ab + aoff + ks * 32);
                    ldsm4(p0, p1, p2, p3, boff0 + ks * 32);
                    ldsm4(q0, q1, q2, q3, boff1 + ks * 32);
                    mma16(d[0][0], d[0][1], d[0][2], d[0][3], a0, a1, a2, a3, p0, p1);
                    mma16(d[1][0], d[1][1], d[1][2], d[1][3], a0, a1, a2, a3, p2, p3);
                    mma16(d[2][0], d[2][1], d[2][2], d[2][3], a0, a1, a2, a3, q0, q1);
                    mma16(d[3][0], d[3][1], d[3][2], d[3][3], a0, a1, a2, a3, q2, q3);
                }
            }

            // epilogue: pair exchange, cell update, fp16 h stage, direct c
            __half* hst = (__half*)(smb + PHST);
#pragma unroll
            for (int t8 = 0; t8 < 4; t8++) {
                float v0 = pr ? d[t8][0] : d[t8][2];
                float v1 = pr ? d[t8][1] : d[t8][3];
                v0 = __shfl_xor_sync(0xffffffffu, v0, 1);
                v1 = __shfl_xor_sync(0xffffffffu, v1, 1);
                float gi, gf, gg, go;
                if (pr) { gi = v0;       gf = v1;       gg = d[t8][2]; go = d[t8][3]; }
                else    { gi = d[t8][0]; gf = d[t8][1]; gg = v0;       go = v1;       }
                int hl = hlb + t8 * 2;
                uint2 gv = *(const uint2*)(gsh + nloc * 144 + hl * 8);
                float2 glo = __half22float2(*(__half2*)&gv.x);
                float2 ghi = __half22float2(*(__half2*)&gv.y);
                gi += glo.x; gf += glo.y; gg += ghi.x; go += ghi.y;
                float cn = sigm(gf) * cold[t8] + sigm(gi) * tanhfast(gg);
                float hn = sigm(go) * tanhfast(cn);
                if (val2) cbase[t8 * 2] = cn;
                hst[nloc * 24 + hl] = __float2half_rn(hn);
            }
            __syncthreads();   // MMA + stage reads done; buffers reusable

            // coalesced h writeout (64 rows x 32B)
            if (t < 128) {
                int row = t >> 1, piece = t & 1;
                int nd = node0 + row;
                if (nd < N) {
                    uint4 v = *(const uint4*)(smb + PHST + row * 48 + piece * 16);
                    *(uint4*)((char*)hw + (size_t)nd * 320 + cg * 32 + piece * 16) = v;
                }
            }
            // prefetch tile ti+2
            if (ti + 2 < nt) {
                int n2 = (slot + (ti + 2) * SLOTS) * MT;
                if (!first) {
#pragma unroll
                    for (int j = 0; j < 5; j++) {
                        int idx = t + 256 * j, row = idx / 20, ch = idx - row * 20;
                        int nd = n2 + row; if (nd >= N) nd = N - 1;
                        CP16(ab + (uint)(row * 336 + ch * 16),
                             (const char*)hr + (size_t)nd * 320 + ch * 16);
                    }
                }
                int nd = n2 + si;
                int sid = (nd < N) ? __ldg(&src[nd * DEG + step]) : 0;
                const char* gs = (const char*)g_g16 + (size_t)sid * 1280 + cg * 128 + sq * 32;
                uint gd = wsh + PG0 + (uint)((ti & 1) * 9216 + si * 144 + sq * 32);
                CP16(gd, gs); CP16(gd + 16, gs + 16);
            }
            CPCOMMIT();
        }

        if (step < DEG - 1) grid_barrier((unsigned)(step + 1) * GRID);
    }
}

// Kernel 4: FFMA2 GEMM, Nc=128 --------------------------------------------
//   mode 1: g_rout = g_hin(fp32) @ W_r^T + b_l
//   mode 2: out    = relu(h_last(fp16, g_ha) @ W_l^T + g_rout)
__global__ void gemm_kernel(const float* __restrict__ B,
                            const float* __restrict__ biasp,
                            float* __restrict__ Cext, int N, int mode) {
    __shared__ float As[16][64];
    __shared__ float Bs[16][64];
    float* C = (mode == 1) ? g_rout : Cext;

    int m0 = blockIdx.y * 64;
    int n0 = blockIdx.x * 64;
    int t  = threadIdx.x;
    int lr = t >> 2, lq = t & 3;
    int tx = t & 15, ty = t >> 4;

    ull acc[4][2];
#pragma unroll
    for (int i = 0; i < 4; i++) { acc[i][0] = 0ull; acc[i][1] = 0ull; }

    for (int kc = 0; kc < FDIM; kc += 16) {
        float4 av = make_float4(0.f, 0.f, 0.f, 0.f);
        int am = m0 + lr;
        if (am < N) {
            if (mode == 1) {
                av = *(const float4*)(g_hin + (size_t)am * FDIM + kc + lq * 4);
            } else {
                uint2 u = *(const uint2*)((const char*)g_ha + (size_t)am * 320 + (kc + lq * 4) * 2);
                float2 f0 = __half22float2(*(__half2*)&u.x);
                float2 f1 = __half22float2(*(__half2*)&u.y);
                av = make_float4(f0.x, f0.y, f1.x, f1.y);
            }
        }
        As[lq * 4 + 0][lr] = av.x; As[lq * 4 + 1][lr] = av.y;
        As[lq * 4 + 2][lr] = av.z; As[lq * 4 + 3][lr] = av.w;

        float4 bv = *(const float4*)(B + (size_t)(n0 + lr) * FDIM + kc + lq * 4);
        Bs[lq * 4 + 0][lr] = bv.x; Bs[lq * 4 + 1][lr] = bv.y;
        Bs[lq * 4 + 2][lr] = bv.z; Bs[lq * 4 + 3][lr] = bv.w;
        __syncthreads();

#pragma unroll
        for (int kk = 0; kk < 16; kk++) {
            float4 a4 = *(const float4*)&As[kk][ty * 4];
            longlong2 b2 = *(const longlong2*)&Bs[kk][tx * 4];
            ull bx = (ull)b2.x, by = (ull)b2.y;
            float a[4] = {a4.x, a4.y, a4.z, a4.w};
#pragma unroll
            for (int i = 0; i < 4; i++) {
                ull a2 = dup2(a[i]);
                acc[i][0] = ffma2(a2, bx, acc[i][0]);
                acc[i][1] = ffma2(a2, by, acc[i][1]);
            }
        }
        __syncthreads();
    }

#pragma unroll
    for (int i = 0; i < 4; i++) {
        int m = m0 + ty * 4 + i;
        if (m < N) {
            float2 lo = unpk(acc[i][0]);
            float2 hi = unpk(acc[i][1]);
            float4 o;
            if (mode == 1) {
                float4 bb = *(const float4*)(biasp + n0 + tx * 4);
                o.x = lo.x + bb.x; o.y = lo.y + bb.y;
                o.z = hi.x + bb.z; o.w = hi.y + bb.w;
            } else {
                float4 rv = *(const float4*)(g_rout + (size_t)m * OUTC + n0 + tx * 4);
                o.x = fmaxf(lo.x + rv.x, 0.f);
                o.y = fmaxf(lo.y + rv.y, 0.f);
                o.z = fmaxf(hi.x + rv.z, 0.f);
                o.w = fmaxf(hi.y + rv.w, 0.f);
            }
            *(float4*)(C + (size_t)m * OUTC + n0 + tx * 4) = o;
        }
    }
}

// Launcher ------------------------------------------------------------------
extern "C" void kernel_launch(void* const* d_in, const int* in_sizes, int n_in,
                              void* d_out, int out_size) {
    const float* x     = (const float*)d_in[0];
    const int*   types = (const int*)d_in[1];
    const int*   eidx  = (const int*)d_in[2];
    const float* emb   = (const float*)d_in[3];
    const float* W_ih  = (const float*)d_in[4];
    const float* W_hh  = (const float*)d_in[5];
    const float* b_ih  = (const float*)d_in[6];
    const float* b_hh  = (const float*)d_in[7];
    const float* W_l   = (const float*)d_in[8];
    const float* b_l   = (const float*)d_in[9];
    const float* W_r   = (const float*)d_in[10];
    float* out = (float*)d_out;

    int N = in_sizes[1];
    const int* srcp = eidx;

    cudaFuncSetAttribute((const void*)tc_pre,
                         cudaFuncAttributeMaxDynamicSharedMemorySize, PRE_SMEM);
    cudaFuncSetAttribute((const void*)lstm_persist,
                         cudaFuncAttributeMaxDynamicSharedMemorySize, PERSIST_SMEM);

    concat_kernel<<<(N * 40 + 255) / 256, 256>>>(x, types, emb, N);   // 1

    tc_pre<<<GRID, 256, PRE_SMEM>>>(W_ih, b_ih, b_hh, N);             // 2

    dim3 g2(2, (N + 63) / 64);
    gemm_kernel<<<g2, 256>>>(W_r, b_l, nullptr, N, 1);                // 3

    reset_kernel<<<1, 1>>>();                                         // 4
    reset_kernel<<<1, 1>>>();                                         // 5

    lstm_persist<<<GRID, 256, PERSIST_SMEM>>>(W_hh, srcp, N);         // 6

    gemm_kernel<<<g2, 256>>>(W_l, nullptr, out, N, 2);                // 7
}